// round 1
// baseline (speedup 1.0000x reference)
#include <cuda_runtime.h>
#include <math.h>

#define M_TOT   8192      // B*N*S rows
#define KDIM    512       // H
#define NDIM    512
#define S_LEN   1024
#define NHEADS  8
#define DHEAD   64
#define GBN     64        // NHEADS * (B*N)

// -------- scratch (device globals; allocation-free rule) --------
__device__ float g_Q[NHEADS * 8 * S_LEN * DHEAD];   // [g][bn][s][d]
__device__ float g_K[NHEADS * 8 * S_LEN * DHEAD];
__device__ float g_V[NHEADS * 8 * S_LEN * DHEAD];
__device__ float g_Ycat[(size_t)M_TOT * NDIM];      // normalized, concat layout
__device__ float g_Gate[(size_t)M_TOT * NDIM];      // silu(X @ W_G)

// =================================================================
// Generic fp32 GEMM, 128x128 tile, BK=8, 256 threads, 8x8 per thread
// MODE 0: C = X @ W_head  -> headed layout g_Q/g_K/g_V (which selects)
// MODE 1: C = silu(X @ W_G) -> g_Gate (row-major)
// MODE 2: C = (g_Gate .* g_Ycat) @ W_O -> Cout (row-major, d_out)
// =================================================================
__device__ __forceinline__ float silu_f(float x) {
    return x / (1.0f + expf(-x));
}

template<int MODE>
__global__ void __launch_bounds__(256) gemm_k(const float* __restrict__ A,
                                              const float* __restrict__ B,
                                              float* __restrict__ Cout,
                                              int which)
{
    __shared__ float As[8][128];
    __shared__ float Bs[8][128];
    const int bm = blockIdx.y * 128;
    const int bn = blockIdx.x * 128;
    const int tid = threadIdx.x;
    const int tx = tid & 15;
    const int ty = tid >> 4;

    float acc[8][8];
#pragma unroll
    for (int i = 0; i < 8; i++)
#pragma unroll
        for (int j = 0; j < 8; j++) acc[i][j] = 0.0f;

    const int arow = tid >> 1, acol = (tid & 1) * 4;
    const int brow = tid >> 5, bcol = (tid & 31) * 4;

    for (int k0 = 0; k0 < KDIM; k0 += 8) {
        float4 av;
        if (MODE == 2) {
            size_t off = (size_t)(bm + arow) * KDIM + k0 + acol;
            float4 a1 = *(const float4*)&g_Gate[off];
            float4 a2 = *(const float4*)&g_Ycat[off];
            av = make_float4(a1.x * a2.x, a1.y * a2.y, a1.z * a2.z, a1.w * a2.w);
        } else {
            av = *(const float4*)&A[(size_t)(bm + arow) * KDIM + k0 + acol];
        }
        As[acol + 0][arow] = av.x;
        As[acol + 1][arow] = av.y;
        As[acol + 2][arow] = av.z;
        As[acol + 3][arow] = av.w;

        float4 bv;
        int cg = bn + bcol;
        if (MODE == 0) {
            // W is [heads][K][64]; column cg -> head cg>>6, dim cg&63
            bv = *(const float4*)&B[(size_t)(cg >> 6) * (KDIM * DHEAD)
                                    + (size_t)(k0 + brow) * DHEAD + (cg & 63)];
        } else {
            bv = *(const float4*)&B[(size_t)(k0 + brow) * NDIM + cg];
        }
        *(float4*)&Bs[brow][bcol] = bv;

        __syncthreads();
#pragma unroll
        for (int kk = 0; kk < 8; kk++) {
            float a[8], b[8];
            *(float4*)&a[0] = *(float4*)&As[kk][ty * 4];
            *(float4*)&a[4] = *(float4*)&As[kk][ty * 4 + 64];
            *(float4*)&b[0] = *(float4*)&Bs[kk][tx * 4];
            *(float4*)&b[4] = *(float4*)&Bs[kk][tx * 4 + 64];
#pragma unroll
            for (int i = 0; i < 8; i++)
#pragma unroll
                for (int j = 0; j < 8; j++)
                    acc[i][j] += a[i] * b[j];
        }
        __syncthreads();
    }

    float* Cq = nullptr;
    if (MODE == 0) Cq = (which == 0) ? g_Q : ((which == 1) ? g_K : g_V);

#pragma unroll
    for (int ih = 0; ih < 2; ih++) {
#pragma unroll
        for (int ii = 0; ii < 4; ii++) {
            int mg = bm + ih * 64 + ty * 4 + ii;
#pragma unroll
            for (int jh = 0; jh < 2; jh++) {
                int cg = bn + jh * 64 + tx * 4;
                float4 v;
                v.x = acc[ih * 4 + ii][jh * 4 + 0];
                v.y = acc[ih * 4 + ii][jh * 4 + 1];
                v.z = acc[ih * 4 + ii][jh * 4 + 2];
                v.w = acc[ih * 4 + ii][jh * 4 + 3];
                if (MODE == 0) {
                    *(float4*)&Cq[(size_t)(cg >> 6) * ((size_t)M_TOT * DHEAD)
                                  + (size_t)mg * DHEAD + (cg & 63)] = v;
                } else if (MODE == 1) {
                    v.x = silu_f(v.x); v.y = silu_f(v.y);
                    v.z = silu_f(v.z); v.w = silu_f(v.w);
                    *(float4*)&g_Gate[(size_t)mg * NDIM + cg] = v;
                } else {
                    *(float4*)&Cout[(size_t)mg * NDIM + cg] = v;
                }
            }
        }
    }
}

// =================================================================
// xpos rotary, in-place on g_Q (scaled) and g_K (inverse-scaled).
// One block per sequence position s; tables computed in double once.
// =================================================================
__global__ void __launch_bounds__(256) rotary_k()
{
    const int s = blockIdx.x;
    __shared__ float sn[32], cs[32], scl[32];
    if (threadIdx.x < 32) {
        int j = threadIdx.x;
        double invf = pow(10000.0, -(double)j / 32.0);
        double ang = (double)s * invf;
        sn[j] = (float)sin(ang);
        cs[j] = (float)cos(ang);
        double sv = ((double)(2 * j) + 0.4 * 64.0) / (1.4 * 64.0);
        scl[j] = (float)pow(sv, (double)s / 512.0);
    }
    __syncthreads();

    for (int t = threadIdx.x; t < GBN * 32; t += blockDim.x) {
        int row = t >> 5;     // g*8+bn
        int j = t & 31;
        size_t base = ((size_t)row * S_LEN + s) * DHEAD + 2 * j;
        float c = cs[j], si = sn[j], sc = scl[j], isc = 1.0f / scl[j];

        float q0 = g_Q[base], q1 = g_Q[base + 1];
        g_Q[base]     = (q0 * c - q1 * si) * sc;
        g_Q[base + 1] = (q1 * c + q0 * si) * sc;

        float k0 = g_K[base], k1 = g_K[base + 1];
        g_K[base]     = (k0 * c - k1 * si) * isc;
        g_K[base + 1] = (k1 * c + k0 * si) * isc;
    }
}

// =================================================================
// Causal retention (decayed QK^T then @V) + fused GroupNorm.
// Block: 64 query rows of one (g,bn). K/V tiles of 32. 256 threads.
// smem: QsT(16K) + KsT(8K) + Vs(8K) + ScT(8K) = 40KB.
// =================================================================
__global__ void __launch_bounds__(256) attn_k(const float* __restrict__ gnw,
                                              const float* __restrict__ gnb)
{
    const int qt  = blockIdx.x;     // 0..15
    const int gbn = blockIdx.y;     // 0..63
    const int g  = gbn >> 3;
    const int bn = gbn & 7;
    const int qbase = qt * 64;

    const float* Qp = g_Q + (size_t)gbn * S_LEN * DHEAD;
    const float* Kp = g_K + (size_t)gbn * S_LEN * DHEAD;
    const float* Vp = g_V + (size_t)gbn * S_LEN * DHEAD;

    __shared__ float QsT[64][64];   // [d][i]
    __shared__ float KsT[64][32];   // [d][j]
    __shared__ float Vs[32][64];    // [j][d]
    __shared__ float ScT[32][64];   // [j][i]

    const int tid = threadIdx.x;
    const int ti = tid & 15, t2 = tid >> 4;
    const int i0 = ti * 4;          // rows (both phases)
    const int j0 = t2 * 2;          // phase-1 score cols
    const int d0 = t2 * 4;          // phase-2 output cols

    // load Q tile, transposed, conflict-free (lane-major over rows)
    {
        int i = tid & 63, cg = (tid >> 6) * 4;
#pragma unroll
        for (int r = 0; r < 4; r++, cg += 16) {
            float4 v = *(const float4*)&Qp[(size_t)(qbase + i) * DHEAD + cg];
            QsT[cg + 0][i] = v.x; QsT[cg + 1][i] = v.y;
            QsT[cg + 2][i] = v.z; QsT[cg + 3][i] = v.w;
        }
    }

    // per-head decay: g_h = 1 - exp(linspace(ln 1/32, ln 1/512, 8))
    double tt = log(1.0 / 32.0) + (double)g * (log(1.0 / 512.0) - log(1.0 / 32.0)) / 7.0;
    float lng = (float)log(1.0 - exp(tt));

    float yacc[4][4];
#pragma unroll
    for (int a = 0; a < 4; a++)
#pragma unroll
        for (int b = 0; b < 4; b++) yacc[a][b] = 0.0f;

    const int nkt = 2 * qt + 2;
    for (int kt = 0; kt < nkt; kt++) {
        const int kbase = kt * 32;
        __syncthreads();   // prev-iter readers done before overwriting tiles

        // K tile transposed
        {
            int j = tid & 31, cg = (tid >> 5) * 4;
#pragma unroll
            for (int r = 0; r < 2; r++, cg += 32) {
                float4 v = *(const float4*)&Kp[(size_t)(kbase + j) * DHEAD + cg];
                KsT[cg + 0][j] = v.x; KsT[cg + 1][j] = v.y;
                KsT[cg + 2][j] = v.z; KsT[cg + 3][j] = v.w;
            }
        }
        // V tile natural, coalesced
        {
#pragma unroll
            for (int r = 0; r < 2; r++) {
                int idx = tid + r * 256;
                int j = idx >> 4, dd = (idx & 15) * 4;
                *(float4*)&Vs[j][dd] =
                    *(const float4*)&Vp[(size_t)(kbase + j) * DHEAD + dd];
            }
        }
        __syncthreads();

        // phase 1: 64x32 score tile, 4x2 per thread
        float sc[4][2];
#pragma unroll
        for (int a = 0; a < 4; a++) { sc[a][0] = 0.0f; sc[a][1] = 0.0f; }
#pragma unroll 16
        for (int d = 0; d < 64; d++) {
            float4 q = *(const float4*)&QsT[d][i0];
            float2 kv = *(const float2*)&KsT[d][j0];
            sc[0][0] += q.x * kv.x; sc[0][1] += q.x * kv.y;
            sc[1][0] += q.y * kv.x; sc[1][1] += q.y * kv.y;
            sc[2][0] += q.z * kv.x; sc[2][1] += q.z * kv.y;
            sc[3][0] += q.w * kv.x; sc[3][1] += q.w * kv.y;
        }
        // decay + causal mask + transposed write (register transpose, float4)
#pragma unroll
        for (int jj = 0; jj < 2; jj++) {
            int kj = kbase + j0 + jj;
            float4 col;
            float* cp = &col.x;
#pragma unroll
            for (int ii = 0; ii < 4; ii++) {
                int qi = qbase + i0 + ii;
                float f = (qi >= kj) ? __expf(lng * (float)(qi - kj)) : 0.0f;
                cp[ii] = sc[ii][jj] * f;
            }
            *(float4*)&ScT[j0 + jj][i0] = col;
        }
        __syncthreads();

        // phase 2: Y += Sc @ V, 4x4 per thread
#pragma unroll 8
        for (int j = 0; j < 32; j++) {
            float4 sv = *(const float4*)&ScT[j][i0];
            float4 vv = *(const float4*)&Vs[j][d0];
            yacc[0][0] += sv.x * vv.x; yacc[0][1] += sv.x * vv.y;
            yacc[0][2] += sv.x * vv.z; yacc[0][3] += sv.x * vv.w;
            yacc[1][0] += sv.y * vv.x; yacc[1][1] += sv.y * vv.y;
            yacc[1][2] += sv.y * vv.z; yacc[1][3] += sv.y * vv.w;
            yacc[2][0] += sv.z * vv.x; yacc[2][1] += sv.z * vv.y;
            yacc[2][2] += sv.z * vv.z; yacc[2][3] += sv.z * vv.w;
            yacc[3][0] += sv.w * vv.x; yacc[3][1] += sv.w * vv.y;
            yacc[3][2] += sv.w * vv.z; yacc[3][3] += sv.w * vv.w;
        }
    }

    // stage Y to smem (reuse QsT) and apply GroupNorm per row
    __syncthreads();
    float (*Ysm)[64] = QsT;
#pragma unroll
    for (int ii = 0; ii < 4; ii++)
        *(float4*)&Ysm[i0 + ii][d0] =
            make_float4(yacc[ii][0], yacc[ii][1], yacc[ii][2], yacc[ii][3]);
    __syncthreads();

    const int wid = tid >> 5, lane = tid & 31;
    float w0 = gnw[g * 64 + lane],      b0 = gnb[g * 64 + lane];
    float w1 = gnw[g * 64 + lane + 32], b1 = gnb[g * 64 + lane + 32];
#pragma unroll
    for (int rr = 0; rr < 8; rr++) {
        int r = wid * 8 + rr;
        float v0 = Ysm[r][lane], v1 = Ysm[r][lane + 32];
        float s = v0 + v1, sq = v0 * v0 + v1 * v1;
#pragma unroll
        for (int o = 16; o; o >>= 1) {
            s  += __shfl_xor_sync(0xffffffffu, s, o);
            sq += __shfl_xor_sync(0xffffffffu, sq, o);
        }
        float mean = s * (1.0f / 64.0f);
        float var = sq * (1.0f / 64.0f) - mean * mean;
        float rstd = rsqrtf(var + 1e-5f);
        size_t obase = ((size_t)bn * S_LEN + (qbase + r)) * NDIM + g * 64;
        g_Ycat[obase + lane]      = (v0 - mean) * rstd * w0 + b0;
        g_Ycat[obase + lane + 32] = (v1 - mean) * rstd * w1 + b1;
    }
}

// =================================================================
extern "C" void kernel_launch(void* const* d_in, const int* in_sizes, int n_in,
                              void* d_out, int out_size)
{
    const float* X   = (const float*)d_in[0];
    const float* WQ  = (const float*)d_in[1];
    const float* WK  = (const float*)d_in[2];
    const float* WV  = (const float*)d_in[3];
    const float* WG  = (const float*)d_in[4];
    const float* WO  = (const float*)d_in[5];
    const float* gnw = (const float*)d_in[6];
    const float* gnb = (const float*)d_in[7];
    float* out = (float*)d_out;

    dim3 gg(NDIM / 128, M_TOT / 128);   // (4, 64)

    gemm_k<0><<<gg, 256>>>(X, WQ, nullptr, 0);
    gemm_k<0><<<gg, 256>>>(X, WK, nullptr, 1);
    gemm_k<0><<<gg, 256>>>(X, WV, nullptr, 2);
    rotary_k<<<S_LEN, 256>>>();
    gemm_k<1><<<gg, 256>>>(X, WG, nullptr, 0);
    attn_k<<<dim3(16, GBN), 256>>>(gnw, gnb);
    gemm_k<2><<<gg, 256>>>(nullptr, WO, out, 0);
}